// round 7
// baseline (speedup 1.0000x reference)
#include <cuda_runtime.h>

// Shapes are fixed for this problem instance.
#define B_SZ 2048
#define H_SZ 2048
#define P_SZ 8192

// Scratch (no cudaMalloc allowed): proj [B, 3H] and gated [B, H]
__device__ float g_proj[(size_t)B_SZ * 3 * H_SZ];
__device__ float g_gated[(size_t)B_SZ * H_SZ];

// ---------------------------------------------------------------------------
// Kernel 1: copy conv_state -> output state region (will be partially
// overwritten by the epilogue for rows in req_pool_indices).
// ---------------------------------------------------------------------------
__global__ void copy_state_kernel(const float4* __restrict__ src,
                                  float4* __restrict__ dst, int n4) {
    int i = blockIdx.x * blockDim.x + threadIdx.x;
    int stride = gridDim.x * blockDim.x;
    for (; i < n4; i += stride) dst[i] = src[i];
}

// ---------------------------------------------------------------------------
// Kernel 2/4: C[m,n] = sum_k A[m,k] * B[n,k]
//   A: [M,K] row-major, B: [N,K] row-major, C: [M,N] row-major.
// Classic 128x128x8 block tile, 256 threads, 8x8 microtile.
// M % 128 == 0, N % 128 == 0, K % 8 == 0 guaranteed by the shapes above.
// ---------------------------------------------------------------------------
__global__ __launch_bounds__(256, 2)
void sgemm_nt_kernel(const float* __restrict__ A, const float* __restrict__ Bm,
                     float* __restrict__ C, int M, int N, int Kd) {
    const int BM = 128, BN = 128, BK = 8;
    __shared__ __align__(16) float As[BK][BM + 4];   // transposed, padded
    __shared__ __align__(16) float Bs[BK][BN + 4];

    int tid = threadIdx.x;
    int tx = tid & 15;    // n direction, 0..15
    int ty = tid >> 4;    // m direction, 0..15
    int mBase = blockIdx.y * BM;
    int nBase = blockIdx.x * BN;

    int loadRow = tid >> 1;        // 0..127
    int loadK   = (tid & 1) * 4;   // 0 or 4

    const float* Aptr = A + (size_t)(mBase + loadRow) * Kd + loadK;
    const float* Bptr = Bm + (size_t)(nBase + loadRow) * Kd + loadK;

    float acc[8][8];
#pragma unroll
    for (int i = 0; i < 8; i++)
#pragma unroll
        for (int j = 0; j < 8; j++) acc[i][j] = 0.f;

    for (int k0 = 0; k0 < Kd; k0 += BK) {
        float4 a4 = *(const float4*)(Aptr + k0);
        float4 b4 = *(const float4*)(Bptr + k0);
        As[loadK + 0][loadRow] = a4.x;
        As[loadK + 1][loadRow] = a4.y;
        As[loadK + 2][loadRow] = a4.z;
        As[loadK + 3][loadRow] = a4.w;
        Bs[loadK + 0][loadRow] = b4.x;
        Bs[loadK + 1][loadRow] = b4.y;
        Bs[loadK + 2][loadRow] = b4.z;
        Bs[loadK + 3][loadRow] = b4.w;
        __syncthreads();
#pragma unroll
        for (int kk = 0; kk < BK; kk++) {
            float4 a0 = *(const float4*)&As[kk][ty * 8];
            float4 a1 = *(const float4*)&As[kk][ty * 8 + 4];
            float4 b0 = *(const float4*)&Bs[kk][tx * 8];
            float4 b1 = *(const float4*)&Bs[kk][tx * 8 + 4];
            float ar[8] = {a0.x, a0.y, a0.z, a0.w, a1.x, a1.y, a1.z, a1.w};
            float br[8] = {b0.x, b0.y, b0.z, b0.w, b1.x, b1.y, b1.z, b1.w};
#pragma unroll
            for (int i = 0; i < 8; i++)
#pragma unroll
                for (int j = 0; j < 8; j++) acc[i][j] = fmaf(ar[i], br[j], acc[i][j]);
        }
        __syncthreads();
    }

#pragma unroll
    for (int i = 0; i < 8; i++) {
        float* Crow = C + (size_t)(mBase + ty * 8 + i) * N + nBase + tx * 8;
        *(float4*)Crow = make_float4(acc[i][0], acc[i][1], acc[i][2], acc[i][3]);
        *(float4*)(Crow + 4) = make_float4(acc[i][4], acc[i][5], acc[i][6], acc[i][7]);
    }
}

// ---------------------------------------------------------------------------
// Kernel 3: conv + gating epilogue.
// proj[b, 0:H] = B_gate, proj[b, H:2H] = C_gate, proj[b, 2H:3H] = x.
// gated[b,h] = C_gate * (c0*w0 + c1*w1 + c2*w2 + (B_gate*x)*w3)
// out_state[idx[b], h, :] = {c1, c2, B_gate*x}
// ---------------------------------------------------------------------------
__global__ void conv_epilogue_kernel(const float* __restrict__ proj,
                                     const float* __restrict__ conv_state,
                                     const int* __restrict__ idx,
                                     const float* __restrict__ conv_w,
                                     float* __restrict__ gated,
                                     float* __restrict__ out_state) {
    int i = blockIdx.x * blockDim.x + threadIdx.x;
    if (i >= B_SZ * H_SZ) return;
    int b = i >> 11;           // / H_SZ
    int h = i & (H_SZ - 1);    // % H_SZ
    int r = idx[b];

    const float* cs = conv_state + ((size_t)r * H_SZ + h) * 3;
    float c0 = cs[0], c1 = cs[1], c2 = cs[2];

    const float* prow = proj + (size_t)b * 3 * H_SZ;
    float Bg = prow[h];
    float Cg = prow[H_SZ + h];
    float x  = prow[2 * H_SZ + h];
    float Bx = Bg * x;

    const float* w = conv_w + h * 4;
    float conv_out = fmaf(c0, w[0], fmaf(c1, w[1], fmaf(c2, w[2], Bx * w[3])));

    gated[i] = Cg * conv_out;

    float* os = out_state + ((size_t)r * H_SZ + h) * 3;
    os[0] = c1;
    os[1] = c2;
    os[2] = Bx;
}

// ---------------------------------------------------------------------------
extern "C" void kernel_launch(void* const* d_in, const int* in_sizes, int n_in,
                              void* d_out, int out_size) {
    const float* hidden     = (const float*)d_in[0];
    const float* conv_state = (const float*)d_in[1];
    const int*   idx        = (const int*)d_in[2];
    const float* w_in       = (const float*)d_in[3];
    const float* w_out      = (const float*)d_in[4];
    const float* conv_w     = (const float*)d_in[5];

    float* y         = (float*)d_out;
    float* out_state = y + (size_t)B_SZ * H_SZ;

    float *proj, *gated;
    cudaGetSymbolAddress((void**)&proj, g_proj);
    cudaGetSymbolAddress((void**)&gated, g_gated);

    // 1) copy conv_state through to the output (rows later overwritten)
    int n4 = (P_SZ * H_SZ * 3) / 4;
    copy_state_kernel<<<2048, 256>>>((const float4*)conv_state,
                                     (float4*)out_state, n4);

    // 2) proj = hidden @ w_in^T   [2048 x 6144]
    sgemm_nt_kernel<<<dim3((3 * H_SZ) / 128, B_SZ / 128), 256>>>(
        hidden, w_in, proj, B_SZ, 3 * H_SZ, H_SZ);

    // 3) conv + gate epilogue, scatter new state rows
    conv_epilogue_kernel<<<(B_SZ * H_SZ + 255) / 256, 256>>>(
        proj, conv_state, idx, conv_w, gated, out_state);

    // 4) y = gated @ w_out^T   [2048 x 2048]
    sgemm_nt_kernel<<<dim3(H_SZ / 128, B_SZ / 128), 256>>>(
        gated, w_out, y, B_SZ, H_SZ, H_SZ);
}

// round 9
// speedup vs baseline: 2.8250x; 2.8250x over previous
#include <cuda_runtime.h>
#include <cuda_bf16.h>
#include <cstdint>

#define B_SZ 2048
#define H_SZ 2048
#define P_SZ 8192
#define K_TOTAL 2048

// ---------------------------------------------------------------------------
// Scratch (__device__ globals; no cudaMalloc allowed)
// ---------------------------------------------------------------------------
__device__ __align__(1024) float g_proj[(size_t)B_SZ * 3 * H_SZ];
__device__ __align__(1024) __nv_bfloat16 g_hid_hi[(size_t)B_SZ * H_SZ];
__device__ __align__(1024) __nv_bfloat16 g_hid_lo[(size_t)B_SZ * H_SZ];
__device__ __align__(1024) __nv_bfloat16 g_win_hi[(size_t)3 * H_SZ * H_SZ];
__device__ __align__(1024) __nv_bfloat16 g_win_lo[(size_t)3 * H_SZ * H_SZ];
__device__ __align__(1024) __nv_bfloat16 g_wout_hi[(size_t)H_SZ * H_SZ];
__device__ __align__(1024) __nv_bfloat16 g_wout_lo[(size_t)H_SZ * H_SZ];
__device__ __align__(1024) __nv_bfloat16 g_gated_hi[(size_t)B_SZ * H_SZ];
__device__ __align__(1024) __nv_bfloat16 g_gated_lo[(size_t)B_SZ * H_SZ];

// ---------------------------------------------------------------------------
// Baseline-PTX helpers (all legal on plain sm_103 target)
// ---------------------------------------------------------------------------
__device__ __forceinline__ uint32_t smem_u32(const void* p) {
    uint32_t a;
    asm("{ .reg .u64 t; cvta.to.shared.u64 t, %1; cvt.u32.u64 %0, t; }"
        : "=r"(a) : "l"(p));
    return a;
}

__device__ __forceinline__ void cp16(uint32_t dst, const void* src) {
    asm volatile("cp.async.cg.shared.global [%0], [%1], 16;"
                 :: "r"(dst), "l"(src));
}
#define CP_COMMIT() asm volatile("cp.async.commit_group;" ::: "memory")
#define CP_WAIT1()  asm volatile("cp.async.wait_group 1;" ::: "memory")

__device__ __forceinline__ void ldsm_x4(uint32_t* r, uint32_t addr) {
    asm volatile("ldmatrix.sync.aligned.m8n8.x4.shared.b16 {%0,%1,%2,%3}, [%4];"
                 : "=r"(r[0]), "=r"(r[1]), "=r"(r[2]), "=r"(r[3]) : "r"(addr));
}

__device__ __forceinline__ void mma_bf16(float* c, const uint32_t* a,
                                         const uint32_t* b) {
    asm volatile(
        "mma.sync.aligned.m16n8k16.row.col.f32.bf16.bf16.f32 "
        "{%0,%1,%2,%3}, {%4,%5,%6,%7}, {%8,%9}, {%0,%1,%2,%3};"
        : "+f"(c[0]), "+f"(c[1]), "+f"(c[2]), "+f"(c[3])
        : "r"(a[0]), "r"(a[1]), "r"(a[2]), "r"(a[3]), "r"(b[0]), "r"(b[1]));
}

// ---------------------------------------------------------------------------
// Split-bf16 warp-MMA GEMM: C[m,n] = sum_k A[m,k]*B[n,k], fp32-emulated via
// D += Ah*Bh + Ah*Bl + Al*Bh. CTA tile 128x128, BK=32, 3-stage cp.async.
// Smem tile layout per stage: Ah@0, Al@8K, Bh@16K, Bl@24K; each tile is
// 128 rows x 64B with XOR swizzle off(r,c4)=r*64+((c4^((r>>1)&3))<<4).
// ---------------------------------------------------------------------------
#define BKI 32
#define NIT (K_TOTAL / BKI)          // 64
#define STG_BYTES 32768
#define NSTG 3
#define SMEM_TOTAL (NSTG * STG_BYTES)

__global__ __launch_bounds__(256)
void mma_gemm_kernel(const __nv_bfloat16* __restrict__ Ah,
                     const __nv_bfloat16* __restrict__ Al,
                     const __nv_bfloat16* __restrict__ Bh,
                     const __nv_bfloat16* __restrict__ Bl,
                     float* __restrict__ C, int Ntotal) {
    extern __shared__ __align__(1024) char smem[];
    const uint32_t sb = smem_u32(smem);
    const int tid = threadIdx.x;
    const int lane = tid & 31;
    const int wid = tid >> 5;
    const int wm = wid & 1;            // 2 warps along M (64 each)
    const int wn = wid >> 1;           // 4 warps along N (32 each)
    const int mBase = blockIdx.y * 128;
    const int nBase = blockIdx.x * 128;

    // ---- cp.async per-thread mapping: 2 chunks per tile-kind per stage ----
    const int ldRow = tid >> 2;        // 0..63 (second rep: +64)
    const int ldC4 = tid & 3;
    const uint32_t sOff1 =
        (uint32_t)ldRow * 64 + ((((uint32_t)ldC4) ^ ((ldRow >> 1) & 3)) << 4);
    const uint32_t sOff2 = sOff1 + 64 * 64;   // +64 rows, same swizzle
    const size_t gStep2 = (size_t)64 * K_TOTAL;
    const __nv_bfloat16* gAh = Ah + (size_t)(mBase + ldRow) * K_TOTAL + ldC4 * 8;
    const __nv_bfloat16* gAl = Al + (size_t)(mBase + ldRow) * K_TOTAL + ldC4 * 8;
    const __nv_bfloat16* gBh = Bh + (size_t)(nBase + ldRow) * K_TOTAL + ldC4 * 8;
    const __nv_bfloat16* gBl = Bl + (size_t)(nBase + ldRow) * K_TOTAL + ldC4 * 8;

#define ISSUE(sst, k0) do {                                                   \
        cp16((sst) + sOff1,          gAh + (k0));                             \
        cp16((sst) + sOff2,          gAh + (k0) + gStep2);                    \
        cp16((sst) + 8192 + sOff1,   gAl + (k0));                             \
        cp16((sst) + 8192 + sOff2,   gAl + (k0) + gStep2);                    \
        cp16((sst) + 16384 + sOff1,  gBh + (k0));                             \
        cp16((sst) + 16384 + sOff2,  gBh + (k0) + gStep2);                    \
        cp16((sst) + 24576 + sOff1,  gBl + (k0));                             \
        cp16((sst) + 24576 + sOff2,  gBl + (k0) + gStep2);                    \
    } while (0)

    // ---- ldmatrix per-thread pre-offsets ----
    uint32_t aBase[4], aSw[4];
    const int rA = lane & 15;
#pragma unroll
    for (int i = 0; i < 4; i++) {
        int row = wm * 64 + i * 16 + rA;
        aBase[i] = (uint32_t)row * 64;
        aSw[i] = (row >> 1) & 3;
    }
    const uint32_t aK = (uint32_t)(lane >> 4);        // 0/1 (k half within 16)
    uint32_t bBase[2], bSw[2];
    const int rB = (lane & 7) + ((lane & 16) ? 8 : 0);
#pragma unroll
    for (int p = 0; p < 2; p++) {
        int row = wn * 32 + p * 16 + rB;
        bBase[p] = (uint32_t)row * 64;
        bSw[p] = (row >> 1) & 3;
    }
    const uint32_t bK = (uint32_t)((lane >> 3) & 1);

    float acc[4][4][4];
#pragma unroll
    for (int i = 0; i < 4; i++)
#pragma unroll
        for (int j = 0; j < 4; j++)
#pragma unroll
            for (int v = 0; v < 4; v++) acc[i][j][v] = 0.f;

    // ---- pipeline prologue ----
    ISSUE(sb + 0 * STG_BYTES, 0);
    CP_COMMIT();
    ISSUE(sb + 1 * STG_BYTES, BKI);
    CP_COMMIT();

    for (int it = 0; it < NIT; ++it) {
        CP_WAIT1();
        __syncthreads();

        if (it + 2 < NIT) {
            uint32_t sn = sb + ((it + 2) % NSTG) * STG_BYTES;
            ISSUE(sn, (it + 2) * BKI);
        }
        CP_COMMIT();

        const uint32_t sst = sb + (it % NSTG) * STG_BYTES;
#pragma unroll
        for (int kk = 0; kk < 2; kk++) {           // two k16 halves of BK=32
            const uint32_t kc = (uint32_t)(kk * 2);
            uint32_t af[16], bhf[8], blf[8];
#pragma unroll
            for (int i = 0; i < 4; i++)
                ldsm_x4(&af[i * 4],
                        sst + aBase[i] + (((aK + kc) ^ aSw[i]) << 4));
#pragma unroll
            for (int p = 0; p < 2; p++)
                ldsm_x4(&bhf[p * 4],
                        sst + 16384 + bBase[p] + (((bK + kc) ^ bSw[p]) << 4));
#pragma unroll
            for (int p = 0; p < 2; p++)
                ldsm_x4(&blf[p * 4],
                        sst + 24576 + bBase[p] + (((bK + kc) ^ bSw[p]) << 4));

#pragma unroll
            for (int i = 0; i < 4; i++)
#pragma unroll
                for (int j = 0; j < 4; j++) {
                    const uint32_t* bfrag = &bhf[(j >> 1) * 4 + (j & 1) * 2];
                    mma_bf16(acc[i][j], &af[i * 4], bfrag);
                    const uint32_t* bfragl = &blf[(j >> 1) * 4 + (j & 1) * 2];
                    mma_bf16(acc[i][j], &af[i * 4], bfragl);
                }

            // Al * Bh (reuse af registers)
#pragma unroll
            for (int i = 0; i < 4; i++)
                ldsm_x4(&af[i * 4],
                        sst + 8192 + aBase[i] + (((aK + kc) ^ aSw[i]) << 4));
#pragma unroll
            for (int i = 0; i < 4; i++)
#pragma unroll
                for (int j = 0; j < 4; j++)
                    mma_bf16(acc[i][j], &af[i * 4],
                             &bhf[(j >> 1) * 4 + (j & 1) * 2]);
        }
        __syncthreads();
    }

    // ---- epilogue: write C ----
    const int row0 = mBase + wm * 64 + (lane >> 2);
    const int col0 = nBase + wn * 32 + (lane & 3) * 2;
#pragma unroll
    for (int i = 0; i < 4; i++) {
#pragma unroll
        for (int j = 0; j < 4; j++) {
            float* p0 = C + (size_t)(row0 + i * 16) * Ntotal + col0 + j * 8;
            float* p1 = p0 + (size_t)8 * Ntotal;
            *(float2*)p0 = make_float2(acc[i][j][0], acc[i][j][1]);
            *(float2*)p1 = make_float2(acc[i][j][2], acc[i][j][3]);
        }
    }
#undef ISSUE
}

// ---------------------------------------------------------------------------
// fp32 -> (bf16 hi, bf16 lo) split
// ---------------------------------------------------------------------------
__global__ void split_bf16_kernel(const float* __restrict__ src,
                                  __nv_bfloat16* __restrict__ hi,
                                  __nv_bfloat16* __restrict__ lo, int n) {
    int i = blockIdx.x * blockDim.x + threadIdx.x;
    int stride = gridDim.x * blockDim.x;
    for (; i < n; i += stride) {
        float v = src[i];
        __nv_bfloat16 h = __float2bfloat16(v);
        hi[i] = h;
        lo[i] = __float2bfloat16(v - __bfloat162float(h));
    }
}

// ---------------------------------------------------------------------------
// conv_state copy-through
// ---------------------------------------------------------------------------
__global__ void copy_state_kernel(const float4* __restrict__ src,
                                  float4* __restrict__ dst, int n4) {
    int i = blockIdx.x * blockDim.x + threadIdx.x;
    int stride = gridDim.x * blockDim.x;
    for (; i < n4; i += stride) dst[i] = src[i];
}

// ---------------------------------------------------------------------------
// conv + gating epilogue; emits gated as bf16 hi/lo splits directly
// ---------------------------------------------------------------------------
__global__ void conv_epilogue_kernel(const float* __restrict__ proj,
                                     const float* __restrict__ conv_state,
                                     const int* __restrict__ idx,
                                     const float* __restrict__ conv_w,
                                     __nv_bfloat16* __restrict__ ghi,
                                     __nv_bfloat16* __restrict__ glo,
                                     float* __restrict__ out_state) {
    int i = blockIdx.x * blockDim.x + threadIdx.x;
    if (i >= B_SZ * H_SZ) return;
    int b = i >> 11;
    int h = i & (H_SZ - 1);
    int r = idx[b];

    const float* cs = conv_state + ((size_t)r * H_SZ + h) * 3;
    float c0 = cs[0], c1 = cs[1], c2 = cs[2];

    const float* prow = proj + (size_t)b * 3 * H_SZ;
    float Bg = prow[h];
    float Cg = prow[H_SZ + h];
    float x  = prow[2 * H_SZ + h];
    float Bx = Bg * x;

    const float* w = conv_w + h * 4;
    float conv_out = fmaf(c0, w[0], fmaf(c1, w[1], fmaf(c2, w[2], Bx * w[3])));
    float g = Cg * conv_out;

    __nv_bfloat16 gh = __float2bfloat16(g);
    ghi[i] = gh;
    glo[i] = __float2bfloat16(g - __bfloat162float(gh));

    float* os = out_state + ((size_t)r * H_SZ + h) * 3;
    os[0] = c1;
    os[1] = c2;
    os[2] = Bx;
}

// ---------------------------------------------------------------------------
extern "C" void kernel_launch(void* const* d_in, const int* in_sizes, int n_in,
                              void* d_out, int out_size) {
    const float* hidden     = (const float*)d_in[0];
    const float* conv_state = (const float*)d_in[1];
    const int*   idx        = (const int*)d_in[2];
    const float* w_in       = (const float*)d_in[3];
    const float* w_out      = (const float*)d_in[4];
    const float* conv_w     = (const float*)d_in[5];

    float* y         = (float*)d_out;
    float* out_state = y + (size_t)B_SZ * H_SZ;

    void *proj, *hid_hi, *hid_lo, *win_hi, *win_lo, *wout_hi, *wout_lo,
         *gat_hi, *gat_lo;
    cudaGetSymbolAddress(&proj, g_proj);
    cudaGetSymbolAddress(&hid_hi, g_hid_hi);
    cudaGetSymbolAddress(&hid_lo, g_hid_lo);
    cudaGetSymbolAddress(&win_hi, g_win_hi);
    cudaGetSymbolAddress(&win_lo, g_win_lo);
    cudaGetSymbolAddress(&wout_hi, g_wout_hi);
    cudaGetSymbolAddress(&wout_lo, g_wout_lo);
    cudaGetSymbolAddress(&gat_hi, g_gated_hi);
    cudaGetSymbolAddress(&gat_lo, g_gated_lo);

    cudaFuncSetAttribute(mma_gemm_kernel,
                         cudaFuncAttributeMaxDynamicSharedMemorySize,
                         SMEM_TOTAL);

    // 1) bf16 hi/lo splits of inputs/weights
    split_bf16_kernel<<<2048, 256>>>(hidden, (__nv_bfloat16*)hid_hi,
                                     (__nv_bfloat16*)hid_lo, B_SZ * H_SZ);
    split_bf16_kernel<<<4096, 256>>>(w_in, (__nv_bfloat16*)win_hi,
                                     (__nv_bfloat16*)win_lo, 3 * H_SZ * H_SZ);
    split_bf16_kernel<<<2048, 256>>>(w_out, (__nv_bfloat16*)wout_hi,
                                     (__nv_bfloat16*)wout_lo, H_SZ * H_SZ);

    // 2) conv_state copy-through (rows overwritten by epilogue)
    copy_state_kernel<<<4096, 256>>>((const float4*)conv_state,
                                     (float4*)out_state, (P_SZ * H_SZ * 3) / 4);

    // 3) proj = hidden @ w_in^T   [2048 x 6144]
    mma_gemm_kernel<<<dim3((3 * H_SZ) / 128, B_SZ / 128), 256, SMEM_TOTAL>>>(
        (const __nv_bfloat16*)hid_hi, (const __nv_bfloat16*)hid_lo,
        (const __nv_bfloat16*)win_hi, (const __nv_bfloat16*)win_lo,
        (float*)proj, 3 * H_SZ);

    // 4) conv + gate epilogue -> gated (bf16 hi/lo), scatter state rows
    conv_epilogue_kernel<<<(B_SZ * H_SZ + 255) / 256, 256>>>(
        (const float*)proj, conv_state, idx, conv_w,
        (__nv_bfloat16*)gat_hi, (__nv_bfloat16*)gat_lo, out_state);

    // 5) y = gated @ w_out^T   [2048 x 2048]
    mma_gemm_kernel<<<dim3(H_SZ / 128, B_SZ / 128), 256, SMEM_TOTAL>>>(
        (const __nv_bfloat16*)gat_hi, (const __nv_bfloat16*)gat_lo,
        (const __nv_bfloat16*)wout_hi, (const __nv_bfloat16*)wout_lo,
        y, H_SZ);
}